// round 12
// baseline (speedup 1.0000x reference)
#include <cuda_runtime.h>
#include <math.h>

#define N_NODES 50000
#define N_EDGES 600000
#define N_GRAPHS 128
#define D 128
#define D_EDGE 64
#define N_LAYERS 4
#define BN_EPS 1e-5f

#define EPB 2048    // edges per block -> 293 blocks
#define ETILE 128   // edges per inner tile (8 grps x 16 edges)
#define NT 64       // nodes per block (node kernel)
#define PCHUNK 400  // nodes per block (pool kernel)

typedef unsigned long long ull;

// packed fp32x2 fma (Blackwell FFMA2)
__device__ __forceinline__ ull fma2(ull a, ull b, ull c) {
    ull d;
    asm("fma.rn.f32x2 %0, %1, %2, %3;" : "=l"(d) : "l"(a), "l"(b), "l"(c));
    return d;
}
__device__ __forceinline__ float sum2(ull v) {
    float a, b;
    asm("mov.b64 {%0,%1}, %2;" : "=f"(a), "=f"(b) : "l"(v));
    return a + b;
}
__device__ __forceinline__ void cp16(void* dst, const void* src) {
    unsigned int d = (unsigned int)__cvta_generic_to_shared(dst);
    asm volatile("cp.async.cg.shared.global [%0], [%1], 16;" :: "r"(d), "l"(src));
}

// ---------------- scratch (no allocations allowed) ----------------
__device__ float g_agg[N_NODES * D];   // zero at load; node kernel re-zeroes each layer
__device__ float g_buf0[N_NODES * D];
__device__ float g_buf1[N_NODES * D];
__device__ float g_counts[N_GRAPHS];

__global__ void zero_counts_kernel() {
    if (threadIdx.x < N_GRAPHS) g_counts[threadIdx.x] = 0.f;
}

// W staging into split-pair conflict-free layout (16B lane stride).
__device__ __forceinline__ void stage_w_split(
    float* fA, float* fB, const float* __restrict__ Wsrc, int nK, int tid, int nthr)
{
    for (int i = tid; i < nK * D; i += nthr) {
        int k = i >> 7, d = i & 127;
        int kq = k >> 2, r = k & 3, half = r & 1;
        int dp = d >> 1, sub = d & 1;
        float* dst = (r < 2) ? fA : fB;
        dst[(kq * 64 + dp) * 4 + sub * 2 + half] = Wsrc[i];
    }
}

// ---------------- edge kernel (pipelined, 16 edges/thread) ----------------
// e = edge_attr @ W_edge + b ; msg = relu(x[src] + e) ; agg[dst] += msg
// 512 threads, 2 blocks/SM. Thread: 2 dims x 16 edges (acc 32 regs).
// W crossbar phases amortized over 16 edges; per-tile barriers halved.
__global__ __launch_bounds__(512, 2) void edge_kernel(
    const float* __restrict__ x_in,
    const int*   __restrict__ edge_index,
    const float* __restrict__ edge_attr,
    const float* __restrict__ W_edge,
    const float* __restrict__ b_edge,
    int layer)
{
    extern __shared__ char dyn[];
    ulonglong2* sWA = (ulonglong2*)dyn;              // 16KB
    ulonglong2* sWB = sWA + 16 * 64;                 // 16KB
    float4*     ea4 = (float4*)(sWB + 16 * 64);      // 2 x 32KB
    int*        sds = (int*)(ea4 + 2 * ETILE * 16);  // 2 x 512B
    int*        sdd = sds + 2 * ETILE;               // 2 x 512B

    const int t   = threadIdx.x;
    const int dp  = t & 63;   // dims 2dp, 2dp+1
    const int grp = t >> 6;   // 8 groups x 16 edges

    stage_w_split((float*)sWA, (float*)sWB,
                  W_edge + (size_t)layer * D_EDGE * D, D_EDGE, t, 512);
    const float2 bias2 = *(const float2*)(b_edge + layer * D + 2 * dp);

    const int e_start = blockIdx.x * EPB;
    const int e_stop  = min(e_start + EPB, N_EDGES);
    const int n_tiles = (e_stop - e_start + ETILE - 1) / ETILE;

#define PREFETCH_TILE(E0, BUF)                                                  \
    do {                                                                        \
        int _e0 = (E0); int _b = (BUF);                                         \
        for (int i = t; i < ETILE * 16; i += 512) {                             \
            int e = _e0 + (i >> 4);                                             \
            float4* dst = &ea4[_b * (ETILE * 16) + i];                          \
            if (e < N_EDGES)                                                    \
                cp16(dst, edge_attr + (size_t)e * D_EDGE + (i & 15) * 4);       \
            else                                                                \
                *dst = make_float4(0.f, 0.f, 0.f, 0.f);                         \
        }                                                                       \
        if (t < 64) {                                                           \
            int half = t >> 5;      /* 0: src row, 1: dst row */                \
            int idx  = (t & 31) * 4;                                            \
            int e = _e0 + idx;                                                  \
            int* dstp = (half ? sdd : sds) + _b * ETILE + idx;                  \
            const int* srcp = edge_index + (size_t)half * N_EDGES + e;          \
            if (e + 3 < N_EDGES) {                                              \
                cp16(dstp, srcp);                                               \
            } else {                                                            \
                for (int k2 = 0; k2 < 4; k2++)                                  \
                    dstp[k2] = (e + k2 < N_EDGES) ? srcp[k2] : 0;               \
            }                                                                   \
        }                                                                       \
    } while (0)

    PREFETCH_TILE(e_start, 0);
    asm volatile("cp.async.commit_group;");

    for (int ti = 0; ti < n_tiles; ti++) {
        asm volatile("cp.async.wait_group 0;");
        __syncthreads();
        const int buf = ti & 1;

        if (ti + 1 < n_tiles)
            PREFETCH_TILE(e_start + (ti + 1) * ETILE, buf ^ 1);
        asm volatile("cp.async.commit_group;");

        ull acc[16][2];
#pragma unroll
        for (int e = 0; e < 16; e++) { acc[e][0] = 0ull; acc[e][1] = 0ull; }

        // single group base -> all LDS inside use immediate offsets
        const float4* eab = ea4 + buf * (ETILE * 16) + grp * 16 * 16;
        const ulonglong2* wAp = sWA + dp;
        const ulonglong2* wBp = sWB + dp;

#pragma unroll
        for (int kq = 0; kq < 16; kq++) {
            ulonglong2 wa = wAp[kq * 64];
            ulonglong2 wb = wBp[kq * 64];
#pragma unroll
            for (int w = 0; w < 4; w++) {          // four waves of 4 edges
                ulonglong2 h[4];
#pragma unroll
                for (int e = 0; e < 4; e++)
                    h[e] = *(const ulonglong2*)&eab[(w * 4 + e) * 16 + kq];
#pragma unroll
                for (int e = 0; e < 4; e++) {
                    int s = w * 4 + e;
                    acc[s][0] = fma2(h[e].x, wa.x, acc[s][0]);
                    acc[s][1] = fma2(h[e].x, wa.y, acc[s][1]);
                    acc[s][0] = fma2(h[e].y, wb.x, acc[s][0]);
                    acc[s][1] = fma2(h[e].y, wb.y, acc[s][1]);
                }
            }
        }

        const int e0 = e_start + ti * ETILE;
        // epilogue in two 8-edge waves (keeps xv at 16 regs)
#pragma unroll
        for (int w = 0; w < 2; w++) {
            float2 xv[8];
#pragma unroll
            for (int e = 0; e < 8; e++) {
                int slot = grp * 16 + w * 8 + e;
                int src = sds[buf * ETILE + slot];
                xv[e] = __ldg((const float2*)(x_in + (size_t)src * D + 2 * dp));
            }
#pragma unroll
            for (int e = 0; e < 8; e++) {
                int slot = grp * 16 + w * 8 + e;
                if (e0 + slot < N_EDGES) {
                    int s = w * 8 + e;
                    int dst = sdd[buf * ETILE + slot];
                    float r0 = fmaxf(sum2(acc[s][0]) + bias2.x + xv[e].x, 0.f);
                    float r1 = fmaxf(sum2(acc[s][1]) + bias2.y + xv[e].y, 0.f);
                    float* p = g_agg + (size_t)dst * D + 2 * dp;
                    asm volatile("red.global.add.v2.f32 [%0], {%1,%2};"
                                 :: "l"(p), "f"(r0), "f"(r1)
                                 : "memory");
                }
            }
        }
    }
#undef PREFETCH_TILE
}

// ---------------- node kernel (fused MLP, fully unrolled GEMM phases) ----------------
__global__ __launch_bounds__(512, 2) void node_kernel(
    const float* __restrict__ x_in,
    float*       __restrict__ x_out,
    const float* __restrict__ W1, const float* __restrict__ b1,
    const float* __restrict__ gamma, const float* __restrict__ beta,
    const float* __restrict__ rm, const float* __restrict__ rv,
    const float* __restrict__ W2, const float* __restrict__ b2,
    int layer, int final_relu)
{
    extern __shared__ float sm[];
    ulonglong2* sWA = (ulonglong2*)sm;          // 32 kq x 64 dp : 32KB
    ulonglong2* sWB = sWA + 32 * 64;            // 32KB
    float*      hs  = (float*)(sWB + 32 * 64);  // 64 nodes x 128 : 32KB

    const int t   = threadIdx.x;
    const int dp  = t & 63;
    const int oct = t >> 6;
    const int nb  = oct * 8;
    const int node0 = blockIdx.x * NT;

    stage_w_split((float*)sWA, (float*)sWB,
                  W1 + (size_t)layer * D * D, D, t, 512);
    for (int i = t; i < NT * D / 4; i += 512) {
        int n = node0 + (i >> 5);
        float4 v = make_float4(0.f, 0.f, 0.f, 0.f);
        if (n < N_NODES) {
            size_t idx = (size_t)n * D + (i & 31) * 4;
            const float4 a = *(const float4*)(x_in + idx);
            const float4 b = *(const float4*)(g_agg + idx);
            v = make_float4(a.x + b.x, a.y + b.y, a.z + b.z, a.w + b.w);
            *(float4*)(g_agg + idx) = make_float4(0.f, 0.f, 0.f, 0.f);
        }
        *(float4*)&hs[i * 4] = v;
    }

    const float2 b1v = *(const float2*)(b1 + layer * D + 2 * dp);
    const float2 b2v = *(const float2*)(b2 + layer * D + 2 * dp);
    const float2 gv  = *(const float2*)(gamma + layer * D + 2 * dp);
    const float2 bv  = *(const float2*)(beta + layer * D + 2 * dp);
    const float2 rmv = *(const float2*)(rm + layer * D + 2 * dp);
    const float2 rvv = *(const float2*)(rv + layer * D + 2 * dp);
    const float sc0 = gv.x * rsqrtf(rvv.x + BN_EPS);
    const float sc1 = gv.y * rsqrtf(rvv.y + BN_EPS);
    const float sh0 = bv.x - rmv.x * sc0;
    const float sh1 = bv.y - rmv.y * sc1;
    __syncthreads();

    const ulonglong2* wAp = sWA + dp;
    const ulonglong2* wBp = sWB + dp;
    const ulonglong2* hp[8];
#pragma unroll
    for (int j = 0; j < 8; j++)
        hp[j] = (const ulonglong2*)&hs[(nb + j) * D];

    // ---- phase 1: mid = relu(BN(hs @ W1 + b1)) ----
    ull acc[8][2];
#pragma unroll
    for (int j = 0; j < 8; j++) { acc[j][0] = 0ull; acc[j][1] = 0ull; }
#pragma unroll
    for (int kq = 0; kq < 32; kq++) {
        ulonglong2 wa = wAp[kq * 64];
        ulonglong2 wb = wBp[kq * 64];
#pragma unroll
        for (int w = 0; w < 2; w++) {
            ulonglong2 h[4];
#pragma unroll
            for (int j = 0; j < 4; j++)
                h[j] = hp[w * 4 + j][kq];
#pragma unroll
            for (int j = 0; j < 4; j++) {
                int s = w * 4 + j;
                acc[s][0] = fma2(h[j].x, wa.x, acc[s][0]);
                acc[s][1] = fma2(h[j].x, wa.y, acc[s][1]);
                acc[s][0] = fma2(h[j].y, wb.x, acc[s][0]);
                acc[s][1] = fma2(h[j].y, wb.y, acc[s][1]);
            }
        }
    }
    float mid[8][2];
#pragma unroll
    for (int j = 0; j < 8; j++) {
        mid[j][0] = fmaxf(fmaf(sum2(acc[j][0]) + b1v.x, sc0, sh0), 0.f);
        mid[j][1] = fmaxf(fmaf(sum2(acc[j][1]) + b1v.y, sc1, sh1), 0.f);
    }
    __syncthreads();

#pragma unroll
    for (int j = 0; j < 8; j++)
        *(float2*)&hs[(nb + j) * D + 2 * dp] = make_float2(mid[j][0], mid[j][1]);
    stage_w_split((float*)sWA, (float*)sWB,
                  W2 + (size_t)layer * D * D, D, t, 512);
    __syncthreads();

    // ---- phase 2: out = mid @ W2 + b2 (+ relu except last layer) ----
#pragma unroll
    for (int j = 0; j < 8; j++) { acc[j][0] = 0ull; acc[j][1] = 0ull; }
#pragma unroll
    for (int kq = 0; kq < 32; kq++) {
        ulonglong2 wa = wAp[kq * 64];
        ulonglong2 wb = wBp[kq * 64];
#pragma unroll
        for (int w = 0; w < 2; w++) {
            ulonglong2 h[4];
#pragma unroll
            for (int j = 0; j < 4; j++)
                h[j] = hp[w * 4 + j][kq];
#pragma unroll
            for (int j = 0; j < 4; j++) {
                int s = w * 4 + j;
                acc[s][0] = fma2(h[j].x, wa.x, acc[s][0]);
                acc[s][1] = fma2(h[j].x, wa.y, acc[s][1]);
                acc[s][0] = fma2(h[j].y, wb.x, acc[s][0]);
                acc[s][1] = fma2(h[j].y, wb.y, acc[s][1]);
            }
        }
    }
#pragma unroll
    for (int j = 0; j < 8; j++) {
        int n = node0 + nb + j;
        if (n < N_NODES) {
            float v0 = sum2(acc[j][0]) + b2v.x;
            float v1 = sum2(acc[j][1]) + b2v.y;
            if (final_relu) { v0 = fmaxf(v0, 0.f); v1 = fmaxf(v1, 0.f); }
            *(float2*)(x_out + (size_t)n * D + 2 * dp) = make_float2(v0, v1);
        }
    }
}

// ---------------- pooling (batch is sorted: run-length accumulate) ----------------
__global__ void pool_kernel(const float* __restrict__ x,
                            const int*   __restrict__ batch,
                            float*       __restrict__ out)
{
    int n0 = blockIdx.x * PCHUNK;
    int n1 = min(n0 + PCHUNK, N_NODES);
    if (n0 >= N_NODES) return;
    int d = threadIdx.x;  // 128 threads
    float acc = 0.f, cnt = 0.f;
    int cur = batch[n0];
    for (int n = n0; n < n1; n++) {
        int g = batch[n];
        if (g != cur) {
            atomicAdd(out + (size_t)cur * D + d, acc);
            if (d == 0) atomicAdd(g_counts + cur, cnt);
            acc = 0.f; cnt = 0.f; cur = g;
        }
        acc += x[(size_t)n * D + d];
        cnt += 1.f;
    }
    atomicAdd(out + (size_t)cur * D + d, acc);
    if (d == 0) atomicAdd(g_counts + cur, cnt);
}

__global__ void div_kernel(float* __restrict__ out) {
    int g = blockIdx.x;
    int t = threadIdx.x;
    out[(size_t)g * D + t] /= fmaxf(g_counts[g], 1.0f);
}

// ---------------- launch ----------------
extern "C" void kernel_launch(void* const* d_in, const int* in_sizes, int n_in,
                              void* d_out, int out_size)
{
    const float* x          = (const float*)d_in[0];
    const int*   edge_index = (const int*)  d_in[1];
    const float* edge_attr  = (const float*)d_in[2];
    const int*   batch      = (const int*)  d_in[3];
    const float* W_edge     = (const float*)d_in[4];
    const float* b_edge     = (const float*)d_in[5];
    const float* W1         = (const float*)d_in[6];
    const float* b1         = (const float*)d_in[7];
    const float* gamma      = (const float*)d_in[8];
    const float* beta       = (const float*)d_in[9];
    const float* rm         = (const float*)d_in[10];
    const float* rv         = (const float*)d_in[11];
    const float* W2         = (const float*)d_in[12];
    const float* b2         = (const float*)d_in[13];
    float* out = (float*)d_out;

    const int EDGE_SMEM = 32768 + 65536 + 1024 + 1024;   // 100352
    cudaFuncSetAttribute((const void*)edge_kernel,
                         cudaFuncAttributeMaxDynamicSharedMemorySize, EDGE_SMEM);
    cudaFuncSetAttribute((const void*)node_kernel,
                         cudaFuncAttributeMaxDynamicSharedMemorySize, 98304);

    void *pb0, *pb1;
    cudaGetSymbolAddress(&pb0, g_buf0);
    cudaGetSymbolAddress(&pb1, g_buf1);
    float* bufs[2] = { (float*)pb0, (float*)pb1 };

    const int edge_blocks = (N_EDGES + EPB - 1) / EPB;
    const int node_blocks = (N_NODES + NT - 1) / NT;
    const int pool_blocks = (N_NODES + PCHUNK - 1) / PCHUNK;

    // zero_counts first: ncu -s 5 lands on edge_kernel (layer 2)
    zero_counts_kernel<<<1, 128>>>();

    const float* cur = x;
    for (int l = 0; l < N_LAYERS; l++) {
        edge_kernel<<<edge_blocks, 512, EDGE_SMEM>>>(cur, edge_index, edge_attr,
                                                     W_edge, b_edge, l);
        float* nxt = bufs[l & 1];
        node_kernel<<<node_blocks, 512, 98304>>>(cur, nxt, W1, b1, gamma, beta,
                                                 rm, rv, W2, b2, l,
                                                 (l != N_LAYERS - 1) ? 1 : 0);
        cur = nxt;
    }

    cudaMemsetAsync(out, 0, (size_t)N_GRAPHS * D * sizeof(float));
    pool_kernel<<<pool_blocks, 128>>>(cur, batch, out);
    div_kernel<<<N_GRAPHS, 128>>>(out);
}

// round 13
// speedup vs baseline: 2.7908x; 2.7908x over previous
#include <cuda_runtime.h>
#include <math.h>

#define N_NODES 50000
#define N_EDGES 600000
#define N_GRAPHS 128
#define D 128
#define D_EDGE 64
#define N_LAYERS 4
#define BN_EPS 1e-5f

#define EPB 2048   // edges per block -> 293 blocks
#define ETILE 64   // edges per inner tile (8 grps x 8 edges) -- E=8 is the reg ceiling
#define NT 64      // nodes per block (node kernel)

typedef unsigned long long ull;

// packed fp32x2 fma (Blackwell FFMA2)
__device__ __forceinline__ ull fma2(ull a, ull b, ull c) {
    ull d;
    asm("fma.rn.f32x2 %0, %1, %2, %3;" : "=l"(d) : "l"(a), "l"(b), "l"(c));
    return d;
}
__device__ __forceinline__ float sum2(ull v) {
    float a, b;
    asm("mov.b64 {%0,%1}, %2;" : "=f"(a), "=f"(b) : "l"(v));
    return a + b;
}
__device__ __forceinline__ void cp16(void* dst, const void* src) {
    unsigned int d = (unsigned int)__cvta_generic_to_shared(dst);
    asm volatile("cp.async.cg.shared.global [%0], [%1], 16;" :: "r"(d), "l"(src));
}

// ---------------- scratch (no allocations allowed) ----------------
__device__ float g_agg[N_NODES * D];   // zero at load; node kernel re-zeroes each layer
__device__ float g_buf0[N_NODES * D];
__device__ float g_buf1[N_NODES * D];
__device__ float g_counts[N_GRAPHS];

__global__ void zero_counts_kernel() {
    if (threadIdx.x < N_GRAPHS) g_counts[threadIdx.x] = 0.f;
}

__global__ void count_kernel(const int* __restrict__ batch) {
    int n = blockIdx.x * 256 + threadIdx.x;
    if (n < N_NODES) atomicAdd(g_counts + batch[n], 1.f);
}

// W staging into split-pair conflict-free layout (16B lane stride).
__device__ __forceinline__ void stage_w_split(
    float* fA, float* fB, const float* __restrict__ Wsrc, int nK, int tid, int nthr)
{
    for (int i = tid; i < nK * D; i += nthr) {
        int k = i >> 7, d = i & 127;
        int kq = k >> 2, r = k & 3, half = r & 1;
        int dp = d >> 1, sub = d & 1;
        float* dst = (r < 2) ? fA : fB;
        dst[(kq * 64 + dp) * 4 + sub * 2 + half] = Wsrc[i];
    }
}

// ---------------- edge kernel (R10 configuration: pipelined, 8 edges/thread) ----------
__global__ __launch_bounds__(512, 2) void edge_kernel(
    const float* __restrict__ x_in,
    const int*   __restrict__ edge_index,
    const float* __restrict__ edge_attr,
    const float* __restrict__ W_edge,
    const float* __restrict__ b_edge,
    int layer)
{
    extern __shared__ char dyn[];
    ulonglong2* sWA = (ulonglong2*)dyn;              // 16KB
    ulonglong2* sWB = sWA + 16 * 64;                 // 16KB
    float4*     ea4 = (float4*)(sWB + 16 * 64);      // 2 x 16KB
    int*        sds = (int*)(ea4 + 2 * ETILE * 16);  // 2 x 256B
    int*        sdd = sds + 2 * ETILE;               // 2 x 256B

    const int t   = threadIdx.x;
    const int dp  = t & 63;   // dims 2dp, 2dp+1
    const int grp = t >> 6;   // 8 groups x 8 edges

    stage_w_split((float*)sWA, (float*)sWB,
                  W_edge + (size_t)layer * D_EDGE * D, D_EDGE, t, 512);
    const float2 bias2 = *(const float2*)(b_edge + layer * D + 2 * dp);

    const int e_start = blockIdx.x * EPB;
    const int e_stop  = min(e_start + EPB, N_EDGES);
    const int n_tiles = (e_stop - e_start + ETILE - 1) / ETILE;

#define PREFETCH_TILE(E0, BUF)                                                  \
    do {                                                                        \
        int _e0 = (E0); int _b = (BUF);                                         \
        for (int i = t; i < ETILE * 16; i += 512) {                             \
            int e = _e0 + (i >> 4);                                             \
            float4* dst = &ea4[_b * (ETILE * 16) + i];                          \
            if (e < N_EDGES)                                                    \
                cp16(dst, edge_attr + (size_t)e * D_EDGE + (i & 15) * 4);       \
            else                                                                \
                *dst = make_float4(0.f, 0.f, 0.f, 0.f);                         \
        }                                                                       \
        if (t < 32) {                                                           \
            int half = t >> 4;                                                  \
            int idx  = (t & 15) * 4;                                            \
            int e = _e0 + idx;                                                  \
            int* dstp = (half ? sdd : sds) + _b * ETILE + idx;                  \
            const int* srcp = edge_index + (size_t)half * N_EDGES + e;          \
            if (e + 3 < N_EDGES) {                                              \
                cp16(dstp, srcp);                                               \
            } else {                                                            \
                for (int k2 = 0; k2 < 4; k2++)                                  \
                    dstp[k2] = (e + k2 < N_EDGES) ? srcp[k2] : 0;               \
            }                                                                   \
        }                                                                       \
    } while (0)

    PREFETCH_TILE(e_start, 0);
    asm volatile("cp.async.commit_group;");

    for (int ti = 0; ti < n_tiles; ti++) {
        asm volatile("cp.async.wait_group 0;");
        __syncthreads();
        const int buf = ti & 1;

        if (ti + 1 < n_tiles)
            PREFETCH_TILE(e_start + (ti + 1) * ETILE, buf ^ 1);
        asm volatile("cp.async.commit_group;");

        // prefetch x[src] gathers for this tile (hidden behind kq compute)
        float2 xv[8];
#pragma unroll
        for (int e = 0; e < 8; e++) {
            int src = sds[buf * ETILE + grp * 8 + e];
            xv[e] = __ldg((const float2*)(x_in + (size_t)src * D + 2 * dp));
        }

        ull acc[8][2];
#pragma unroll
        for (int e = 0; e < 8; e++) { acc[e][0] = 0ull; acc[e][1] = 0ull; }

        const float4* ea = ea4 + buf * (ETILE * 16);
        const ulonglong2* hp[8];
#pragma unroll
        for (int e = 0; e < 8; e++)
            hp[e] = (const ulonglong2*)&ea[(grp * 8 + e) * 16];
        const ulonglong2* wAp = sWA + dp;
        const ulonglong2* wBp = sWB + dp;

#pragma unroll
        for (int kq = 0; kq < 16; kq++) {
            ulonglong2 wa = wAp[kq * 64];
            ulonglong2 wb = wBp[kq * 64];
#pragma unroll
            for (int w = 0; w < 2; w++) {
                ulonglong2 h[4];
#pragma unroll
                for (int e = 0; e < 4; e++)
                    h[e] = hp[w * 4 + e][kq];
#pragma unroll
                for (int e = 0; e < 4; e++) {
                    int s = w * 4 + e;
                    acc[s][0] = fma2(h[e].x, wa.x, acc[s][0]);
                    acc[s][1] = fma2(h[e].x, wa.y, acc[s][1]);
                    acc[s][0] = fma2(h[e].y, wb.x, acc[s][0]);
                    acc[s][1] = fma2(h[e].y, wb.y, acc[s][1]);
                }
            }
        }

        const int e0 = e_start + ti * ETILE;
#pragma unroll
        for (int e = 0; e < 8; e++) {
            int slot = grp * 8 + e;
            if (e0 + slot < N_EDGES) {
                int dst = sdd[buf * ETILE + slot];
                float r0 = fmaxf(sum2(acc[e][0]) + bias2.x + xv[e].x, 0.f);
                float r1 = fmaxf(sum2(acc[e][1]) + bias2.y + xv[e].y, 0.f);
                float* p = g_agg + (size_t)dst * D + 2 * dp;
                asm volatile("red.global.add.v2.f32 [%0], {%1,%2};"
                             :: "l"(p), "f"(r0), "f"(r1)
                             : "memory");
            }
        }
    }
#undef PREFETCH_TILE
}

// ---------------- node kernel (fused MLP; last layer also does mean-pool) ----------
__global__ __launch_bounds__(512, 2) void node_kernel(
    const float* __restrict__ x_in,
    float*       __restrict__ x_out,
    const float* __restrict__ W1, const float* __restrict__ b1,
    const float* __restrict__ gamma, const float* __restrict__ beta,
    const float* __restrict__ rm, const float* __restrict__ rv,
    const float* __restrict__ W2, const float* __restrict__ b2,
    const int*   __restrict__ batch,
    float*       __restrict__ pool_out,
    int layer, int final_relu, int do_pool)
{
    extern __shared__ float sm[];
    ulonglong2* sWA = (ulonglong2*)sm;          // 32 kq x 64 dp : 32KB
    ulonglong2* sWB = sWA + 32 * 64;            // 32KB
    float*      hs  = (float*)(sWB + 32 * 64);  // 64 nodes x 128 : 32KB

    const int t   = threadIdx.x;
    const int dp  = t & 63;
    const int oct = t >> 6;
    const int nb  = oct * 8;
    const int node0 = blockIdx.x * NT;

    stage_w_split((float*)sWA, (float*)sWB,
                  W1 + (size_t)layer * D * D, D, t, 512);
    for (int i = t; i < NT * D / 4; i += 512) {
        int n = node0 + (i >> 5);
        float4 v = make_float4(0.f, 0.f, 0.f, 0.f);
        if (n < N_NODES) {
            size_t idx = (size_t)n * D + (i & 31) * 4;
            const float4 a = *(const float4*)(x_in + idx);
            const float4 b = *(const float4*)(g_agg + idx);
            v = make_float4(a.x + b.x, a.y + b.y, a.z + b.z, a.w + b.w);
            *(float4*)(g_agg + idx) = make_float4(0.f, 0.f, 0.f, 0.f);
        }
        *(float4*)&hs[i * 4] = v;
    }

    const float2 b1v = *(const float2*)(b1 + layer * D + 2 * dp);
    const float2 b2v = *(const float2*)(b2 + layer * D + 2 * dp);
    const float2 gv  = *(const float2*)(gamma + layer * D + 2 * dp);
    const float2 bv  = *(const float2*)(beta + layer * D + 2 * dp);
    const float2 rmv = *(const float2*)(rm + layer * D + 2 * dp);
    const float2 rvv = *(const float2*)(rv + layer * D + 2 * dp);
    const float sc0 = gv.x * rsqrtf(rvv.x + BN_EPS);
    const float sc1 = gv.y * rsqrtf(rvv.y + BN_EPS);
    const float sh0 = bv.x - rmv.x * sc0;
    const float sh1 = bv.y - rmv.y * sc1;
    __syncthreads();

    const ulonglong2* wAp = sWA + dp;
    const ulonglong2* wBp = sWB + dp;
    const ulonglong2* hp[8];
#pragma unroll
    for (int j = 0; j < 8; j++)
        hp[j] = (const ulonglong2*)&hs[(nb + j) * D];

    // ---- phase 1: mid = relu(BN(hs @ W1 + b1)) ----
    ull acc[8][2];
#pragma unroll
    for (int j = 0; j < 8; j++) { acc[j][0] = 0ull; acc[j][1] = 0ull; }
#pragma unroll
    for (int kq = 0; kq < 32; kq++) {
        ulonglong2 wa = wAp[kq * 64];
        ulonglong2 wb = wBp[kq * 64];
#pragma unroll
        for (int w = 0; w < 2; w++) {
            ulonglong2 h[4];
#pragma unroll
            for (int j = 0; j < 4; j++)
                h[j] = hp[w * 4 + j][kq];
#pragma unroll
            for (int j = 0; j < 4; j++) {
                int s = w * 4 + j;
                acc[s][0] = fma2(h[j].x, wa.x, acc[s][0]);
                acc[s][1] = fma2(h[j].x, wa.y, acc[s][1]);
                acc[s][0] = fma2(h[j].y, wb.x, acc[s][0]);
                acc[s][1] = fma2(h[j].y, wb.y, acc[s][1]);
            }
        }
    }
    float mid[8][2];
#pragma unroll
    for (int j = 0; j < 8; j++) {
        mid[j][0] = fmaxf(fmaf(sum2(acc[j][0]) + b1v.x, sc0, sh0), 0.f);
        mid[j][1] = fmaxf(fmaf(sum2(acc[j][1]) + b1v.y, sc1, sh1), 0.f);
    }
    __syncthreads();

#pragma unroll
    for (int j = 0; j < 8; j++)
        *(float2*)&hs[(nb + j) * D + 2 * dp] = make_float2(mid[j][0], mid[j][1]);
    stage_w_split((float*)sWA, (float*)sWB,
                  W2 + (size_t)layer * D * D, D, t, 512);
    __syncthreads();

    // ---- phase 2: out = mid @ W2 + b2 (+ relu except last layer) ----
#pragma unroll
    for (int j = 0; j < 8; j++) { acc[j][0] = 0ull; acc[j][1] = 0ull; }
#pragma unroll
    for (int kq = 0; kq < 32; kq++) {
        ulonglong2 wa = wAp[kq * 64];
        ulonglong2 wb = wBp[kq * 64];
#pragma unroll
        for (int w = 0; w < 2; w++) {
            ulonglong2 h[4];
#pragma unroll
            for (int j = 0; j < 4; j++)
                h[j] = hp[w * 4 + j][kq];
#pragma unroll
            for (int j = 0; j < 4; j++) {
                int s = w * 4 + j;
                acc[s][0] = fma2(h[j].x, wa.x, acc[s][0]);
                acc[s][1] = fma2(h[j].x, wa.y, acc[s][1]);
                acc[s][0] = fma2(h[j].y, wb.x, acc[s][0]);
                acc[s][1] = fma2(h[j].y, wb.y, acc[s][1]);
            }
        }
    }

    if (!do_pool) {
#pragma unroll
        for (int j = 0; j < 8; j++) {
            int n = node0 + nb + j;
            if (n < N_NODES) {
                float v0 = sum2(acc[j][0]) + b2v.x;
                float v1 = sum2(acc[j][1]) + b2v.y;
                if (final_relu) { v0 = fmaxf(v0, 0.f); v1 = fmaxf(v1, 0.f); }
                *(float2*)(x_out + (size_t)n * D + 2 * dp) = make_float2(v0, v1);
            }
        }
    } else {
        // fused global-mean-pool accumulate (batch sorted: run-length per 8 nodes)
        float a0 = 0.f, a1 = 0.f;
        int curg = -1;
#pragma unroll
        for (int j = 0; j < 8; j++) {
            int n = node0 + nb + j;
            if (n < N_NODES) {
                int g = __ldg(batch + n);
                if (g != curg) {
                    if (curg >= 0) {
                        float* p = pool_out + (size_t)curg * D + 2 * dp;
                        asm volatile("red.global.add.v2.f32 [%0], {%1,%2};"
                                     :: "l"(p), "f"(a0), "f"(a1) : "memory");
                    }
                    a0 = 0.f; a1 = 0.f; curg = g;
                }
                a0 += sum2(acc[j][0]) + b2v.x;
                a1 += sum2(acc[j][1]) + b2v.y;
            }
        }
        if (curg >= 0) {
            float* p = pool_out + (size_t)curg * D + 2 * dp;
            asm volatile("red.global.add.v2.f32 [%0], {%1,%2};"
                         :: "l"(p), "f"(a0), "f"(a1) : "memory");
        }
    }
}

__global__ void div_kernel(float* __restrict__ out) {
    int g = blockIdx.x;
    int t = threadIdx.x;
    out[(size_t)g * D + t] /= fmaxf(g_counts[g], 1.0f);
}

// ---------------- launch ----------------
extern "C" void kernel_launch(void* const* d_in, const int* in_sizes, int n_in,
                              void* d_out, int out_size)
{
    const float* x          = (const float*)d_in[0];
    const int*   edge_index = (const int*)  d_in[1];
    const float* edge_attr  = (const float*)d_in[2];
    const int*   batch      = (const int*)  d_in[3];
    const float* W_edge     = (const float*)d_in[4];
    const float* b_edge     = (const float*)d_in[5];
    const float* W1         = (const float*)d_in[6];
    const float* b1         = (const float*)d_in[7];
    const float* gamma      = (const float*)d_in[8];
    const float* beta       = (const float*)d_in[9];
    const float* rm         = (const float*)d_in[10];
    const float* rv         = (const float*)d_in[11];
    const float* W2         = (const float*)d_in[12];
    const float* b2         = (const float*)d_in[13];
    float* out = (float*)d_out;

    const int EDGE_SMEM = 16384 + 16384 + 32768 + 512 + 512;   // 66560
    cudaFuncSetAttribute((const void*)edge_kernel,
                         cudaFuncAttributeMaxDynamicSharedMemorySize, EDGE_SMEM);
    cudaFuncSetAttribute((const void*)node_kernel,
                         cudaFuncAttributeMaxDynamicSharedMemorySize, 98304);

    void *pb0, *pb1;
    cudaGetSymbolAddress(&pb0, g_buf0);
    cudaGetSymbolAddress(&pb1, g_buf1);
    float* bufs[2] = { (float*)pb0, (float*)pb1 };

    const int edge_blocks = (N_EDGES + EPB - 1) / EPB;
    const int node_blocks = (N_NODES + NT - 1) / NT;

    // zero_counts first: ncu -s 5 lands on edge_kernel (layer 2)
    zero_counts_kernel<<<1, 128>>>();

    const float* cur = x;
    for (int l = 0; l < N_LAYERS; l++) {
        edge_kernel<<<edge_blocks, 512, EDGE_SMEM>>>(cur, edge_index, edge_attr,
                                                     W_edge, b_edge, l);
        float* nxt = bufs[l & 1];
        int last = (l == N_LAYERS - 1);
        if (last)
            cudaMemsetAsync(out, 0, (size_t)N_GRAPHS * D * sizeof(float));
        node_kernel<<<node_blocks, 512, 98304>>>(cur, nxt, W1, b1, gamma, beta,
                                                 rm, rv, W2, b2, batch, out, l,
                                                 last ? 0 : 1, last ? 1 : 0);
        cur = nxt;
    }

    count_kernel<<<(N_NODES + 255) / 256, 256>>>(batch);
    div_kernel<<<N_GRAPHS, 128>>>(out);
}

// round 14
// speedup vs baseline: 2.8218x; 1.0111x over previous
#include <cuda_runtime.h>
#include <math.h>

#define N_NODES 50000
#define N_EDGES 600000
#define N_GRAPHS 128
#define D 128
#define D_EDGE 64
#define N_LAYERS 4
#define BN_EPS 1e-5f

#define EPB 1024   // edges per block -> 586 blocks = 1 wave at 4 blocks/SM
#define ETILE 32   // edges per inner tile (4 grps x 8 edges)
#define NT 64      // nodes per block (node kernel)

typedef unsigned long long ull;

// packed fp32x2 fma (Blackwell FFMA2)
__device__ __forceinline__ ull fma2(ull a, ull b, ull c) {
    ull d;
    asm("fma.rn.f32x2 %0, %1, %2, %3;" : "=l"(d) : "l"(a), "l"(b), "l"(c));
    return d;
}
__device__ __forceinline__ float sum2(ull v) {
    float a, b;
    asm("mov.b64 {%0,%1}, %2;" : "=f"(a), "=f"(b) : "l"(v));
    return a + b;
}
__device__ __forceinline__ void cp16(void* dst, const void* src) {
    unsigned int d = (unsigned int)__cvta_generic_to_shared(dst);
    asm volatile("cp.async.cg.shared.global [%0], [%1], 16;" :: "r"(d), "l"(src));
}

// ---------------- scratch (no allocations allowed) ----------------
__device__ float g_agg[N_NODES * D];   // zero at load; node kernel re-zeroes each layer
__device__ float g_buf0[N_NODES * D];
__device__ float g_buf1[N_NODES * D];
__device__ float g_counts[N_GRAPHS];

__global__ void zero_counts_kernel() {
    if (threadIdx.x < N_GRAPHS) g_counts[threadIdx.x] = 0.f;
}

__global__ void count_kernel(const int* __restrict__ batch) {
    int n = blockIdx.x * 256 + threadIdx.x;
    if (n < N_NODES) atomicAdd(g_counts + batch[n], 1.f);
}

// W staging into split-pair conflict-free layout (16B lane stride).
__device__ __forceinline__ void stage_w_split(
    float* fA, float* fB, const float* __restrict__ Wsrc, int nK, int tid, int nthr)
{
    for (int i = tid; i < nK * D; i += nthr) {
        int k = i >> 7, d = i & 127;
        int kq = k >> 2, r = k & 3, half = r & 1;
        int dp = d >> 1, sub = d & 1;
        float* dst = (r < 2) ? fA : fB;
        dst[(kq * 64 + dp) * 4 + sub * 2 + half] = Wsrc[i];
    }
}

// ---------------- edge kernel (pipelined, 256 thr x 4 blocks/SM) ----------------
// e = edge_attr @ W_edge + b ; msg = relu(x[src] + e) ; agg[dst] += msg
// Thread: 2 dims x 8 edges. 8-warp barrier domains, 4 independent streams/SM.
__global__ __launch_bounds__(256, 4) void edge_kernel(
    const float* __restrict__ x_in,
    const int*   __restrict__ edge_index,
    const float* __restrict__ edge_attr,
    const float* __restrict__ W_edge,
    const float* __restrict__ b_edge,
    int layer)
{
    extern __shared__ char dyn[];
    ulonglong2* sWA = (ulonglong2*)dyn;              // 16KB
    ulonglong2* sWB = sWA + 16 * 64;                 // 16KB
    float4*     ea4 = (float4*)(sWB + 16 * 64);      // 2 x 8KB
    int*        sds = (int*)(ea4 + 2 * ETILE * 16);  // 2 x 128B
    int*        sdd = sds + 2 * ETILE;               // 2 x 128B

    const int t   = threadIdx.x;
    const int dp  = t & 63;   // dims 2dp, 2dp+1
    const int grp = t >> 6;   // 4 groups x 8 edges

    stage_w_split((float*)sWA, (float*)sWB,
                  W_edge + (size_t)layer * D_EDGE * D, D_EDGE, t, 256);
    const float2 bias2 = *(const float2*)(b_edge + layer * D + 2 * dp);

    const int e_start = blockIdx.x * EPB;
    const int e_stop  = min(e_start + EPB, N_EDGES);
    const int n_tiles = (e_stop - e_start + ETILE - 1) / ETILE;

#define PREFETCH_TILE(E0, BUF)                                                  \
    do {                                                                        \
        int _e0 = (E0); int _b = (BUF);                                         \
        for (int i = t; i < ETILE * 16; i += 256) {                             \
            int e = _e0 + (i >> 4);                                             \
            float4* dst = &ea4[_b * (ETILE * 16) + i];                          \
            if (e < N_EDGES)                                                    \
                cp16(dst, edge_attr + (size_t)e * D_EDGE + (i & 15) * 4);       \
            else                                                                \
                *dst = make_float4(0.f, 0.f, 0.f, 0.f);                         \
        }                                                                       \
        if (t < 16) {                                                           \
            int half = t >> 3;      /* 0: src row, 1: dst row */                \
            int idx  = (t & 7) * 4;                                             \
            int e = _e0 + idx;                                                  \
            int* dstp = (half ? sdd : sds) + _b * ETILE + idx;                  \
            const int* srcp = edge_index + (size_t)half * N_EDGES + e;          \
            if (e + 3 < N_EDGES) {                                              \
                cp16(dstp, srcp);                                               \
            } else {                                                            \
                for (int k2 = 0; k2 < 4; k2++)                                  \
                    dstp[k2] = (e + k2 < N_EDGES) ? srcp[k2] : 0;               \
            }                                                                   \
        }                                                                       \
    } while (0)

    PREFETCH_TILE(e_start, 0);
    asm volatile("cp.async.commit_group;");

    for (int ti = 0; ti < n_tiles; ti++) {
        asm volatile("cp.async.wait_group 0;");
        __syncthreads();
        const int buf = ti & 1;

        if (ti + 1 < n_tiles)
            PREFETCH_TILE(e_start + (ti + 1) * ETILE, buf ^ 1);
        asm volatile("cp.async.commit_group;");

        // prefetch x[src] gathers for this tile (hidden behind kq compute)
        float2 xv[8];
#pragma unroll
        for (int e = 0; e < 8; e++) {
            int src = sds[buf * ETILE + grp * 8 + e];
            xv[e] = __ldg((const float2*)(x_in + (size_t)src * D + 2 * dp));
        }

        ull acc[8][2];
#pragma unroll
        for (int e = 0; e < 8; e++) { acc[e][0] = 0ull; acc[e][1] = 0ull; }

        const float4* ea = ea4 + buf * (ETILE * 16);
        const ulonglong2* hp[8];
#pragma unroll
        for (int e = 0; e < 8; e++)
            hp[e] = (const ulonglong2*)&ea[(grp * 8 + e) * 16];
        const ulonglong2* wAp = sWA + dp;
        const ulonglong2* wBp = sWB + dp;

#pragma unroll
        for (int kq = 0; kq < 16; kq++) {
            ulonglong2 wa = wAp[kq * 64];
            ulonglong2 wb = wBp[kq * 64];
#pragma unroll
            for (int w = 0; w < 2; w++) {
                ulonglong2 h[4];
#pragma unroll
                for (int e = 0; e < 4; e++)
                    h[e] = hp[w * 4 + e][kq];
#pragma unroll
                for (int e = 0; e < 4; e++) {
                    int s = w * 4 + e;
                    acc[s][0] = fma2(h[e].x, wa.x, acc[s][0]);
                    acc[s][1] = fma2(h[e].x, wa.y, acc[s][1]);
                    acc[s][0] = fma2(h[e].y, wb.x, acc[s][0]);
                    acc[s][1] = fma2(h[e].y, wb.y, acc[s][1]);
                }
            }
        }

        const int e0 = e_start + ti * ETILE;
#pragma unroll
        for (int e = 0; e < 8; e++) {
            int slot = grp * 8 + e;
            if (e0 + slot < N_EDGES) {
                int dst = sdd[buf * ETILE + slot];
                float r0 = fmaxf(sum2(acc[e][0]) + bias2.x + xv[e].x, 0.f);
                float r1 = fmaxf(sum2(acc[e][1]) + bias2.y + xv[e].y, 0.f);
                float* p = g_agg + (size_t)dst * D + 2 * dp;
                asm volatile("red.global.add.v2.f32 [%0], {%1,%2};"
                             :: "l"(p), "f"(r0), "f"(r1)
                             : "memory");
            }
        }
    }
#undef PREFETCH_TILE
}

// ---------------- node kernel (fused MLP; last layer also does mean-pool) ----------
__global__ __launch_bounds__(512, 2) void node_kernel(
    const float* __restrict__ x_in,
    float*       __restrict__ x_out,
    const float* __restrict__ W1, const float* __restrict__ b1,
    const float* __restrict__ gamma, const float* __restrict__ beta,
    const float* __restrict__ rm, const float* __restrict__ rv,
    const float* __restrict__ W2, const float* __restrict__ b2,
    const int*   __restrict__ batch,
    float*       __restrict__ pool_out,
    int layer, int final_relu, int do_pool)
{
    extern __shared__ float sm[];
    ulonglong2* sWA = (ulonglong2*)sm;          // 32 kq x 64 dp : 32KB
    ulonglong2* sWB = sWA + 32 * 64;            // 32KB
    float*      hs  = (float*)(sWB + 32 * 64);  // 64 nodes x 128 : 32KB

    const int t   = threadIdx.x;
    const int dp  = t & 63;
    const int oct = t >> 6;
    const int nb  = oct * 8;
    const int node0 = blockIdx.x * NT;

    stage_w_split((float*)sWA, (float*)sWB,
                  W1 + (size_t)layer * D * D, D, t, 512);
    for (int i = t; i < NT * D / 4; i += 512) {
        int n = node0 + (i >> 5);
        float4 v = make_float4(0.f, 0.f, 0.f, 0.f);
        if (n < N_NODES) {
            size_t idx = (size_t)n * D + (i & 31) * 4;
            const float4 a = *(const float4*)(x_in + idx);
            const float4 b = *(const float4*)(g_agg + idx);
            v = make_float4(a.x + b.x, a.y + b.y, a.z + b.z, a.w + b.w);
            *(float4*)(g_agg + idx) = make_float4(0.f, 0.f, 0.f, 0.f);
        }
        *(float4*)&hs[i * 4] = v;
    }

    const float2 b1v = *(const float2*)(b1 + layer * D + 2 * dp);
    const float2 b2v = *(const float2*)(b2 + layer * D + 2 * dp);
    const float2 gv  = *(const float2*)(gamma + layer * D + 2 * dp);
    const float2 bv  = *(const float2*)(beta + layer * D + 2 * dp);
    const float2 rmv = *(const float2*)(rm + layer * D + 2 * dp);
    const float2 rvv = *(const float2*)(rv + layer * D + 2 * dp);
    const float sc0 = gv.x * rsqrtf(rvv.x + BN_EPS);
    const float sc1 = gv.y * rsqrtf(rvv.y + BN_EPS);
    const float sh0 = bv.x - rmv.x * sc0;
    const float sh1 = bv.y - rmv.y * sc1;
    __syncthreads();

    const ulonglong2* wAp = sWA + dp;
    const ulonglong2* wBp = sWB + dp;
    const ulonglong2* hp[8];
#pragma unroll
    for (int j = 0; j < 8; j++)
        hp[j] = (const ulonglong2*)&hs[(nb + j) * D];

    // ---- phase 1: mid = relu(BN(hs @ W1 + b1)) ----
    ull acc[8][2];
#pragma unroll
    for (int j = 0; j < 8; j++) { acc[j][0] = 0ull; acc[j][1] = 0ull; }
#pragma unroll
    for (int kq = 0; kq < 32; kq++) {
        ulonglong2 wa = wAp[kq * 64];
        ulonglong2 wb = wBp[kq * 64];
#pragma unroll
        for (int w = 0; w < 2; w++) {
            ulonglong2 h[4];
#pragma unroll
            for (int j = 0; j < 4; j++)
                h[j] = hp[w * 4 + j][kq];
#pragma unroll
            for (int j = 0; j < 4; j++) {
                int s = w * 4 + j;
                acc[s][0] = fma2(h[j].x, wa.x, acc[s][0]);
                acc[s][1] = fma2(h[j].x, wa.y, acc[s][1]);
                acc[s][0] = fma2(h[j].y, wb.x, acc[s][0]);
                acc[s][1] = fma2(h[j].y, wb.y, acc[s][1]);
            }
        }
    }
    float mid[8][2];
#pragma unroll
    for (int j = 0; j < 8; j++) {
        mid[j][0] = fmaxf(fmaf(sum2(acc[j][0]) + b1v.x, sc0, sh0), 0.f);
        mid[j][1] = fmaxf(fmaf(sum2(acc[j][1]) + b1v.y, sc1, sh1), 0.f);
    }
    __syncthreads();

#pragma unroll
    for (int j = 0; j < 8; j++)
        *(float2*)&hs[(nb + j) * D + 2 * dp] = make_float2(mid[j][0], mid[j][1]);
    stage_w_split((float*)sWA, (float*)sWB,
                  W2 + (size_t)layer * D * D, D, t, 512);
    __syncthreads();

    // ---- phase 2: out = mid @ W2 + b2 (+ relu except last layer) ----
#pragma unroll
    for (int j = 0; j < 8; j++) { acc[j][0] = 0ull; acc[j][1] = 0ull; }
#pragma unroll
    for (int kq = 0; kq < 32; kq++) {
        ulonglong2 wa = wAp[kq * 64];
        ulonglong2 wb = wBp[kq * 64];
#pragma unroll
        for (int w = 0; w < 2; w++) {
            ulonglong2 h[4];
#pragma unroll
            for (int j = 0; j < 4; j++)
                h[j] = hp[w * 4 + j][kq];
#pragma unroll
            for (int j = 0; j < 4; j++) {
                int s = w * 4 + j;
                acc[s][0] = fma2(h[j].x, wa.x, acc[s][0]);
                acc[s][1] = fma2(h[j].x, wa.y, acc[s][1]);
                acc[s][0] = fma2(h[j].y, wb.x, acc[s][0]);
                acc[s][1] = fma2(h[j].y, wb.y, acc[s][1]);
            }
        }
    }

    if (!do_pool) {
#pragma unroll
        for (int j = 0; j < 8; j++) {
            int n = node0 + nb + j;
            if (n < N_NODES) {
                float v0 = sum2(acc[j][0]) + b2v.x;
                float v1 = sum2(acc[j][1]) + b2v.y;
                if (final_relu) { v0 = fmaxf(v0, 0.f); v1 = fmaxf(v1, 0.f); }
                *(float2*)(x_out + (size_t)n * D + 2 * dp) = make_float2(v0, v1);
            }
        }
    } else {
        // fused global-mean-pool accumulate (batch sorted: run-length per 8 nodes)
        float a0 = 0.f, a1 = 0.f;
        int curg = -1;
#pragma unroll
        for (int j = 0; j < 8; j++) {
            int n = node0 + nb + j;
            if (n < N_NODES) {
                int g = __ldg(batch + n);
                if (g != curg) {
                    if (curg >= 0) {
                        float* p = pool_out + (size_t)curg * D + 2 * dp;
                        asm volatile("red.global.add.v2.f32 [%0], {%1,%2};"
                                     :: "l"(p), "f"(a0), "f"(a1) : "memory");
                    }
                    a0 = 0.f; a1 = 0.f; curg = g;
                }
                a0 += sum2(acc[j][0]) + b2v.x;
                a1 += sum2(acc[j][1]) + b2v.y;
            }
        }
        if (curg >= 0) {
            float* p = pool_out + (size_t)curg * D + 2 * dp;
            asm volatile("red.global.add.v2.f32 [%0], {%1,%2};"
                         :: "l"(p), "f"(a0), "f"(a1) : "memory");
        }
    }
}

__global__ void div_kernel(float* __restrict__ out) {
    int g = blockIdx.x;
    int t = threadIdx.x;
    out[(size_t)g * D + t] /= fmaxf(g_counts[g], 1.0f);
}

// ---------------- launch ----------------
extern "C" void kernel_launch(void* const* d_in, const int* in_sizes, int n_in,
                              void* d_out, int out_size)
{
    const float* x          = (const float*)d_in[0];
    const int*   edge_index = (const int*)  d_in[1];
    const float* edge_attr  = (const float*)d_in[2];
    const int*   batch      = (const int*)  d_in[3];
    const float* W_edge     = (const float*)d_in[4];
    const float* b_edge     = (const float*)d_in[5];
    const float* W1         = (const float*)d_in[6];
    const float* b1         = (const float*)d_in[7];
    const float* gamma      = (const float*)d_in[8];
    const float* beta       = (const float*)d_in[9];
    const float* rm         = (const float*)d_in[10];
    const float* rv         = (const float*)d_in[11];
    const float* W2         = (const float*)d_in[12];
    const float* b2         = (const float*)d_in[13];
    float* out = (float*)d_out;

    const int EDGE_SMEM = 16384 + 16384 + 16384 + 256 + 256;   // 49664
    cudaFuncSetAttribute((const void*)edge_kernel,
                         cudaFuncAttributeMaxDynamicSharedMemorySize, EDGE_SMEM);
    cudaFuncSetAttribute((const void*)node_kernel,
                         cudaFuncAttributeMaxDynamicSharedMemorySize, 98304);

    void *pb0, *pb1;
    cudaGetSymbolAddress(&pb0, g_buf0);
    cudaGetSymbolAddress(&pb1, g_buf1);
    float* bufs[2] = { (float*)pb0, (float*)pb1 };

    const int edge_blocks = (N_EDGES + EPB - 1) / EPB;   // 586
    const int node_blocks = (N_NODES + NT - 1) / NT;

    // zero_counts first: ncu -s 5 lands on edge_kernel (layer 2)
    zero_counts_kernel<<<1, 128>>>();

    const float* cur = x;
    for (int l = 0; l < N_LAYERS; l++) {
        edge_kernel<<<edge_blocks, 256, EDGE_SMEM>>>(cur, edge_index, edge_attr,
                                                     W_edge, b_edge, l);
        float* nxt = bufs[l & 1];
        int last = (l == N_LAYERS - 1);
        if (last)
            cudaMemsetAsync(out, 0, (size_t)N_GRAPHS * D * sizeof(float));
        node_kernel<<<node_blocks, 512, 98304>>>(cur, nxt, W1, b1, gamma, beta,
                                                 rm, rv, W2, b2, batch, out, l,
                                                 last ? 0 : 1, last ? 1 : 0);
        cur = nxt;
    }

    count_kernel<<<(N_NODES + 255) / 256, 256>>>(batch);
    div_kernel<<<N_GRAPHS, 128>>>(out);
}